// round 15
// baseline (speedup 1.0000x reference)
#include <cuda_runtime.h>
#include <cuda_fp16.h>
#include <math.h>
#include <stdint.h>

// Problem constants
#define BB 4
#define SS 2048
#define EE 1024
#define HH 16
#define DH 64
#define FFD 4096
#define MM (BB * SS)          // 8192 tokens
#define E3 (3 * EE)           // 3072

// ---------------------------------------------------------------------------
// Scratch buffers (device globals; allocation-free)
// ---------------------------------------------------------------------------
__device__ __align__(128) __half g_xn[(size_t)MM * EE];
__device__ __align__(128) __half g_qkv[(size_t)MM * E3];
__device__ __align__(128) __half g_attn[(size_t)MM * EE];
__device__ __align__(128) float  g_x2[(size_t)MM * EE];
__device__ __align__(128) __half g_fc1[(size_t)MM * FFD];
__device__ __align__(128) __half g_wc[(size_t)12 * 1024 * 1024];

// ---------------------------------------------------------------------------
// Helpers
// ---------------------------------------------------------------------------
__device__ __forceinline__ uint32_t smem_u32(const void* p) {
    uint32_t a;
    asm("{ .reg .u64 t; cvta.to.shared.u64 t, %1; cvt.u32.u64 %0, t; }"
        : "=r"(a) : "l"(p));
    return a;
}
__device__ __forceinline__ void cp16(uint32_t s, const void* g) {
    asm volatile("cp.async.cg.shared.global [%0], [%1], 16;" :: "r"(s), "l"(g));
}
#define CP_COMMIT asm volatile("cp.async.commit_group;" ::: "memory")
#define CP_WAIT2  asm volatile("cp.async.wait_group 2;" ::: "memory")
#define CP_WAIT0  asm volatile("cp.async.wait_group 0;" ::: "memory")

__device__ __forceinline__ void mmah(float c[4], const uint32_t a[4],
                                     uint32_t b0, uint32_t b1) {
    asm volatile(
        "mma.sync.aligned.m16n8k16.row.col.f32.f16.f16.f32 "
        "{%0,%1,%2,%3}, {%4,%5,%6,%7}, {%8,%9}, {%0,%1,%2,%3};"
        : "+f"(c[0]), "+f"(c[1]), "+f"(c[2]), "+f"(c[3])
        : "r"(a[0]), "r"(a[1]), "r"(a[2]), "r"(a[3]), "r"(b0), "r"(b1));
}
#define LDSM4(r, addr) \
    asm volatile("ldmatrix.sync.aligned.m8n8.x4.shared.b16 {%0,%1,%2,%3}, [%4];" \
        : "=r"((r)[0]), "=r"((r)[1]), "=r"((r)[2]), "=r"((r)[3]) : "r"(addr))
#define LDSM4T(r, addr) \
    asm volatile("ldmatrix.sync.aligned.m8n8.x4.trans.shared.b16 {%0,%1,%2,%3}, [%4];" \
        : "=r"((r)[0]), "=r"((r)[1]), "=r"((r)[2]), "=r"((r)[3]) : "r"(addr))

__device__ __forceinline__ uint32_t packf2(float lo, float hi) {
    __half2 h = __floats2half2_rn(lo, hi);
    return *(uint32_t*)&h;
}

// ---------------------------------------------------------------------------
// Fused weight convert fp32 -> fp16
// ---------------------------------------------------------------------------
#define M1 (1024 * 1024)
__global__ void __launch_bounds__(256) cvt_all_kernel(
    const float* __restrict__ w_qkv, const float* __restrict__ w_o,
    const float* __restrict__ w_fc1, const float* __restrict__ w_fc2,
    __half* __restrict__ out) {
    int i = (blockIdx.x * 256 + threadIdx.x) * 8;
    const float* src;
    int ofs;
    if (i < 3 * M1)       { src = w_qkv; ofs = i; }
    else if (i < 4 * M1)  { src = w_o;   ofs = i - 3 * M1; }
    else if (i < 8 * M1)  { src = w_fc1; ofs = i - 4 * M1; }
    else                  { src = w_fc2; ofs = i - 8 * M1; }
    float4 v0 = *(const float4*)(src + ofs);
    float4 v1 = *(const float4*)(src + ofs + 4);
    __half2 h[4];
    h[0] = __floats2half2_rn(v0.x, v0.y);
    h[1] = __floats2half2_rn(v0.z, v0.w);
    h[2] = __floats2half2_rn(v1.x, v1.y);
    h[3] = __floats2half2_rn(v1.z, v1.w);
    *(uint2*)(out + i)     = make_uint2(*(uint32_t*)&h[0], *(uint32_t*)&h[1]);
    *(uint2*)(out + i + 4) = make_uint2(*(uint32_t*)&h[2], *(uint32_t*)&h[3]);
}

// ---------------------------------------------------------------------------
// FP16 mma.sync GEMM NT: CTA 256x128x64(halves), 512 threads (16 warps,
// 4Mx4N, warp 64x32), 4-stage cp.async ring, one sync per K-iter.
//   EPI 0: + bias -> half   EPI 1: + bias + residual -> float
//   EPI 2: + bias, exact GELU -> half
// ---------------------------------------------------------------------------
#define BM 256
#define BN 128
#define BK 64
#define SROWB 144
#define ASTGB (BM * SROWB)             // 36864 B
#define STGB (ASTGB + BN * SROWB)      // 55296 B per stage
#define NSTG 4
#define GEMM_SMEM (NSTG * STGB)        // 221184 B

template <int EPI>
__global__ void __launch_bounds__(512, 1) gemm_mma(
    const __half* __restrict__ A, const __half* __restrict__ W,
    const float* __restrict__ bias, const float* __restrict__ res,
    void* __restrict__ Cv, int M, int N, int K)
{
    extern __shared__ char smemraw[];
    const int tid = threadIdx.x;
    const int bm = blockIdx.y * BM;
    const int bn = blockIdx.x * BN;
    const uint32_t sbase = smem_u32(smemraw);

    const int w = tid >> 5, lane = tid & 31;
    const int t = lane & 3;
    const int g = lane >> 2;
    const int wm = (w & 3) * 64;       // 4 M warps, warp covers 64 rows
    const int wn = (w >> 2) * 32;      // 4 N warps, warp covers 32 cols

    const uint32_t aLd = (wm + (lane & 15)) * SROWB + ((lane >> 4) << 4);
    const uint32_t bLd = (wn + (lane & 7) + ((lane >> 4) << 3)) * SROWB
                         + (((lane >> 3) & 1) << 4);

    const __half* Ag = A + (size_t)bm * K;
    const __half* Wg = W + (size_t)bn * K;

    float acc[4][4][4];
    #pragma unroll
    for (int mi = 0; mi < 4; mi++)
        #pragma unroll
        for (int ni = 0; ni < 4; ni++)
            #pragma unroll
            for (int j = 0; j < 4; j++) acc[mi][ni][j] = 0.0f;

    auto load_tile = [&](int stg, int kt) {
        const uint32_t dA = sbase + stg * STGB;
        const uint32_t dB = dA + ASTGB;
        const int kofs = kt * BK;
        #pragma unroll
        for (int i = 0; i < 4; i++) {          // A: 256 rows x 8 chunks
            int chunk = tid + i * 512;
            int r = chunk >> 3, c = chunk & 7;
            cp16(dA + r * SROWB + c * 16, Ag + (size_t)r * K + kofs + c * 8);
        }
        #pragma unroll
        for (int i = 0; i < 2; i++) {          // B: 128 rows x 8 chunks
            int chunk = tid + i * 512;
            int r = chunk >> 3, c = chunk & 7;
            cp16(dB + r * SROWB + c * 16, Wg + (size_t)r * K + kofs + c * 8);
        }
    };

    const int nk = K / BK;
    load_tile(0, 0); CP_COMMIT;
    load_tile(1, 1); CP_COMMIT;
    load_tile(2, 2); CP_COMMIT;

    for (int kt = 0; kt < nk; kt++) {
        const int s = kt & 3;
        CP_WAIT2;               // tile kt landed (this thread)
        __syncthreads();        // visible to all; stage (kt+3)&3 freed
        const int nxt = kt + 3;
        if (nxt < nk) load_tile(nxt & 3, nxt);
        CP_COMMIT;

        const uint32_t aBase = sbase + s * STGB + aLd;
        const uint32_t bBase = sbase + s * STGB + ASTGB + bLd;

        #pragma unroll
        for (int ks = 0; ks < 4; ks++) {
            const uint32_t ko = ks * 32;
            uint32_t a[4][4], bq[2][4];
            #pragma unroll
            for (int mi = 0; mi < 4; mi++)
                LDSM4(a[mi], aBase + mi * 16 * SROWB + ko);
            #pragma unroll
            for (int p = 0; p < 2; p++)
                LDSM4(bq[p], bBase + p * 16 * SROWB + ko);
            #pragma unroll
            for (int mi = 0; mi < 4; mi++)
                #pragma unroll
                for (int p = 0; p < 2; p++) {
                    mmah(acc[mi][2 * p],     a[mi], bq[p][0], bq[p][1]);
                    mmah(acc[mi][2 * p + 1], a[mi], bq[p][2], bq[p][3]);
                }
        }
    }

    // epilogue
    float bb[4][2];
    #pragma unroll
    for (int ni = 0; ni < 4; ni++) {
        int col = bn + wn + ni * 8 + t * 2;
        bb[ni][0] = __ldg(bias + col);
        bb[ni][1] = __ldg(bias + col + 1);
    }
    #pragma unroll
    for (int mi = 0; mi < 4; mi++) {
        #pragma unroll
        for (int h = 0; h < 2; h++) {
            const int row = bm + wm + mi * 16 + g + h * 8;
            #pragma unroll
            for (int ni = 0; ni < 4; ni++) {
                const int col = bn + wn + ni * 8 + t * 2;
                float o0 = acc[mi][ni][h * 2 + 0] + bb[ni][0];
                float o1 = acc[mi][ni][h * 2 + 1] + bb[ni][1];
                if (EPI == 0) {
                    *(__half2*)((__half*)Cv + (size_t)row * N + col) =
                        __floats2half2_rn(o0, o1);
                } else if (EPI == 1) {
                    const float2 rv = *(const float2*)(res + (size_t)row * N + col);
                    *(float2*)((float*)Cv + (size_t)row * N + col) =
                        make_float2(o0 + rv.x, o1 + rv.y);
                } else {
                    o0 = 0.5f * o0 * (1.0f + erff(o0 * 0.70710678118654752f));
                    o1 = 0.5f * o1 * (1.0f + erff(o1 * 0.70710678118654752f));
                    *(__half2*)((__half*)Cv + (size_t)row * N + col) =
                        __floats2half2_rn(o0, o1);
                }
            }
        }
    }
}

// ---------------------------------------------------------------------------
// LayerNorm: one block per token row of 1024; fp16 output
// ---------------------------------------------------------------------------
__global__ void __launch_bounds__(256) ln_kernel(const float* __restrict__ x,
                                                 const float* __restrict__ g,
                                                 const float* __restrict__ b,
                                                 __half* __restrict__ out) {
    int row = blockIdx.x;
    const float4* xr = (const float4*)(x + (size_t)row * EE);
    float4 v = xr[threadIdx.x];
    float s  = v.x + v.y + v.z + v.w;
    float sq = v.x * v.x + v.y * v.y + v.z * v.z + v.w * v.w;
    #pragma unroll
    for (int o = 16; o; o >>= 1) {
        s  += __shfl_xor_sync(0xffffffffu, s,  o);
        sq += __shfl_xor_sync(0xffffffffu, sq, o);
    }
    __shared__ float ss[8], ssq[8];
    int w = threadIdx.x >> 5, ln = threadIdx.x & 31;
    if (ln == 0) { ss[w] = s; ssq[w] = sq; }
    __syncthreads();
    if (w == 0) {
        s  = (ln < 8) ? ss[ln]  : 0.0f;
        sq = (ln < 8) ? ssq[ln] : 0.0f;
        #pragma unroll
        for (int o = 4; o; o >>= 1) {
            s  += __shfl_xor_sync(0xffffffffu, s,  o);
            sq += __shfl_xor_sync(0xffffffffu, sq, o);
        }
        if (ln == 0) { ss[0] = s; ssq[0] = sq; }
    }
    __syncthreads();
    float mean = ss[0] * (1.0f / EE);
    float var  = ssq[0] * (1.0f / EE) - mean * mean;
    float rstd = rsqrtf(var + 1e-5f);
    int c = threadIdx.x * 4;
    float4 gg = *(const float4*)(g + c);
    float4 bb = *(const float4*)(b + c);
    __half2 h0 = __floats2half2_rn((v.x - mean) * rstd * gg.x + bb.x,
                                   (v.y - mean) * rstd * gg.y + bb.y);
    __half2 h1 = __floats2half2_rn((v.z - mean) * rstd * gg.z + bb.z,
                                   (v.w - mean) * rstd * gg.w + bb.w);
    *(uint2*)(out + (size_t)row * EE + c) =
        make_uint2(*(uint32_t*)&h0, *(uint32_t*)&h1);
}

// ---------------------------------------------------------------------------
// FP16 tensor-core flash attention; register-resident P; LUT periodic mask;
// double-buffered cp.async K/V; reversed qb order; guarded O-rescale.
// ---------------------------------------------------------------------------
#define AS2 72
#define ASB (AS2 * 2)
#define KVB (128 * ASB)
#define ATT_SMEM ((128 + 256) * ASB + 256)

__global__ void __launch_bounds__(256, 2) attn_tc(const __half* __restrict__ qkv,
                                                  const int* __restrict__ tdp,
                                                  __half* __restrict__ out) {
    extern __shared__ char smemraw[];
    __half* Qs  = (__half*)smemraw;
    __half* KV0 = Qs + 128 * AS2;
    __half* kmaskS = KV0 + 2 * 128 * AS2;

    const int qb = gridDim.x - 1 - blockIdx.x;   // longest tiles first
    const int bh = blockIdx.y;
    const int b = bh >> 4, h = bh & 15;
    const int TD = tdp[0];
    const int tid = threadIdx.x, w = tid >> 5, lane = tid & 31;
    const int g = lane >> 2, t = lane & 3;

    const size_t base = (size_t)b * SS * E3 + (size_t)h * DH;
    const uint32_t kvBase = smem_u32(KV0);

    const uint32_t qLd = smem_u32(Qs) +
        (w * 16 + (lane & 15)) * ASB + ((lane >> 4) << 4);
    const uint32_t kLd0 = kvBase +
        ((lane & 7) + ((lane >> 4) << 3)) * ASB + (((lane >> 3) & 1) << 4);
    const uint32_t vLd0 = kvBase + 64 * ASB +
        (lane & 15) * ASB + ((lane >> 4) << 4);

    for (int i = tid; i < 128 * 8; i += 256) {
        int r = i >> 3, c = (i & 7) * 8;
        *(uint4*)(Qs + r * AS2 + c) =
            *(const uint4*)(qkv + base + (size_t)(qb * 128 + r) * E3 + c);
    }

    auto load_kv = [&](int kb, int buf) {
        const uint32_t dst = kvBase + buf * KVB;
        #pragma unroll
        for (int i = 0; i < 2; i++) {
            int chunk = tid + i * 256;
            int r = chunk >> 3, cB = (chunk & 7) << 4;
            size_t off = base + (size_t)(kb * 64 + r) * E3 + (cB >> 1);
            cp16(dst + r * ASB + cB,            qkv + off + EE);
            cp16(dst + 64 * ASB + r * ASB + cB, qkv + off + 2 * EE);
        }
        if (tid < 64) {
            int col = kb * 64 + tid;
            kmaskS[buf * 64 + tid] =
                ((col % TD) == TD - 1) ? __float2half(0.0f) : __float2half(1.0f);
        }
    };

    float m0 = -1e30f, m1 = -1e30f, l0 = 0.0f, l1 = 0.0f;
    float o[8][4];
    #pragma unroll
    for (int ni = 0; ni < 8; ni++)
        #pragma unroll
        for (int j = 0; j < 4; j++) o[ni][j] = 0.0f;

    const int ig0 = qb * 128 + w * 16 + g;
    const int ig1 = ig0 + 8;
    const int nkt = 2 * qb + 2;

    load_kv(0, 0); CP_COMMIT;

    for (int kb = 0; kb < nkt; kb++) {
        const int buf = kb & 1;
        CP_WAIT0;
        __syncthreads();
        if (kb + 1 < nkt) load_kv(kb + 1, buf ^ 1);
        CP_COMMIT;

        const uint32_t kLd = kLd0 + buf * KVB;
        const uint32_t vLd = vLd0 + buf * KVB;

        float s[8][4];
        #pragma unroll
        for (int ni = 0; ni < 8; ni++)
            #pragma unroll
            for (int j = 0; j < 4; j++) s[ni][j] = 0.0f;

        #pragma unroll
        for (int ks = 0; ks < 4; ks++) {
            const uint32_t ko = ks * 32;
            uint32_t aq[4];
            LDSM4(aq, qLd + ko);
            #pragma unroll
            for (int p = 0; p < 4; p++) {
                uint32_t bk[4];
                LDSM4(bk, kLd + p * 16 * ASB + ko);
                mmah(s[2 * p],     aq, bk[0], bk[1]);
                mmah(s[2 * p + 1], aq, bk[2], bk[3]);
            }
        }

        if (kb >= nkt - 2) {
            const int colb = kb * 64 + t * 2;
            #pragma unroll
            for (int ni = 0; ni < 8; ni++) {
                #pragma unroll
                for (int j = 0; j < 2; j++) {
                    const int col = colb + ni * 8 + j;
                    s[ni][j]     = (col > ig0) ? -1e30f : s[ni][j] * 0.125f;
                    s[ni][2 + j] = (col > ig1) ? -1e30f : s[ni][2 + j] * 0.125f;
                }
            }
        } else {
            #pragma unroll
            for (int ni = 0; ni < 8; ni++)
                #pragma unroll
                for (int j = 0; j < 4; j++) s[ni][j] *= 0.125f;
        }

        float rm0 = -1e30f, rm1 = -1e30f;
        #pragma unroll
        for (int ni = 0; ni < 8; ni++) {
            rm0 = fmaxf(rm0, fmaxf(s[ni][0], s[ni][1]));
            rm1 = fmaxf(rm1, fmaxf(s[ni][2], s[ni][3]));
        }
        #pragma unroll
        for (int ofs = 1; ofs < 4; ofs <<= 1) {
            rm0 = fmaxf(rm0, __shfl_xor_sync(0xffffffffu, rm0, ofs));
            rm1 = fmaxf(rm1, __shfl_xor_sync(0xffffffffu, rm1, ofs));
        }
        const float nm0 = fmaxf(m0, rm0), nm1 = fmaxf(m1, rm1);
        const float a0 = __expf(m0 - nm0), a1 = __expf(m1 - nm1);

        const __half2* km = (const __half2*)(kmaskS + buf * 64) + t;
        float rs0 = 0.0f, rs1 = 0.0f;
        #pragma unroll
        for (int ni = 0; ni < 8; ni++) {
            const float2 mk = __half22float2(km[ni * 4]);
            s[ni][0] = __expf(s[ni][0] - nm0) * mk.x;
            s[ni][1] = __expf(s[ni][1] - nm0) * mk.y;
            s[ni][2] = __expf(s[ni][2] - nm1) * mk.x;
            s[ni][3] = __expf(s[ni][3] - nm1) * mk.y;
            rs0 += s[ni][0] + s[ni][1];
            rs1 += s[ni][2] + s[ni][3];
        }
        #pragma unroll
        for (int ofs = 1; ofs < 4; ofs <<= 1) {
            rs0 += __shfl_xor_sync(0xffffffffu, rs0, ofs);
            rs1 += __shfl_xor_sync(0xffffffffu, rs1, ofs);
        }
        l0 = l0 * a0 + rs0;
        l1 = l1 * a1 + rs1;
        // rescale O only when the running max actually changed
        if (nm0 > m0 || nm1 > m1) {
            #pragma unroll
            for (int ni = 0; ni < 8; ni++) {
                o[ni][0] *= a0; o[ni][1] *= a0;
                o[ni][2] *= a1; o[ni][3] *= a1;
            }
        }
        m0 = nm0; m1 = nm1;

        #pragma unroll
        for (int ks = 0; ks < 4; ks++) {
            uint32_t a[4];
            a[0] = packf2(s[2 * ks][0],     s[2 * ks][1]);
            a[1] = packf2(s[2 * ks][2],     s[2 * ks][3]);
            a[2] = packf2(s[2 * ks + 1][0], s[2 * ks + 1][1]);
            a[3] = packf2(s[2 * ks + 1][2], s[2 * ks + 1][3]);
            const uint32_t vBase = vLd + ks * 16 * ASB;
            #pragma unroll
            for (int db = 0; db < 4; db++) {
                uint32_t bv[4];
                LDSM4T(bv, vBase + db * 32);
                mmah(o[2 * db],     a, bv[0], bv[1]);
                mmah(o[2 * db + 1], a, bv[2], bv[3]);
            }
        }
    }

    const float inv0 = 1.0f / l0, inv1 = 1.0f / l1;
    const size_t r0o = ((size_t)(b * SS + qb * 128 + w * 16 + g)) * EE + h * DH;
    const size_t r1o = r0o + 8 * EE;
    #pragma unroll
    for (int ni = 0; ni < 8; ni++) {
        const int c = ni * 8 + t * 2;
        *(__half2*)(out + r0o + c) = __floats2half2_rn(o[ni][0] * inv0, o[ni][1] * inv0);
        *(__half2*)(out + r1o + c) = __floats2half2_rn(o[ni][2] * inv1, o[ni][3] * inv1);
    }
}

// ---------------------------------------------------------------------------
// Launch
// ---------------------------------------------------------------------------
extern "C" void kernel_launch(void* const* d_in, const int* in_sizes, int n_in,
                              void* d_out, int out_size) {
    const float* x      = (const float*)d_in[0];
    const int*   td     = (const int*)d_in[1];
    const float* ln1_g  = (const float*)d_in[2];
    const float* ln1_b  = (const float*)d_in[3];
    const float* ln2_g  = (const float*)d_in[4];
    const float* ln2_b  = (const float*)d_in[5];
    const float* w_qkv  = (const float*)d_in[6];
    const float* b_qkv  = (const float*)d_in[7];
    const float* w_o    = (const float*)d_in[8];
    const float* b_o    = (const float*)d_in[9];
    const float* w_fc1  = (const float*)d_in[10];
    const float* b_fc1  = (const float*)d_in[11];
    const float* w_fc2  = (const float*)d_in[12];
    const float* b_fc2  = (const float*)d_in[13];
    float* out = (float*)d_out;

    __half *xn, *qkvb, *attnb, *fc1b, *wc;
    float *x2;
    cudaGetSymbolAddress((void**)&xn,    g_xn);
    cudaGetSymbolAddress((void**)&qkvb,  g_qkv);
    cudaGetSymbolAddress((void**)&attnb, g_attn);
    cudaGetSymbolAddress((void**)&x2,    g_x2);
    cudaGetSymbolAddress((void**)&fc1b,  g_fc1);
    cudaGetSymbolAddress((void**)&wc,    g_wc);

    __half* wc_qkv = wc;
    __half* wc_o   = wc + (size_t)3 * M1;
    __half* wc_fc1 = wc + (size_t)4 * M1;
    __half* wc_fc2 = wc + (size_t)8 * M1;

    cudaFuncSetAttribute(gemm_mma<0>, cudaFuncAttributeMaxDynamicSharedMemorySize, GEMM_SMEM);
    cudaFuncSetAttribute(gemm_mma<1>, cudaFuncAttributeMaxDynamicSharedMemorySize, GEMM_SMEM);
    cudaFuncSetAttribute(gemm_mma<2>, cudaFuncAttributeMaxDynamicSharedMemorySize, GEMM_SMEM);
    cudaFuncSetAttribute(attn_tc, cudaFuncAttributeMaxDynamicSharedMemorySize, ATT_SMEM);

    // 0. Convert all weights to fp16, one launch
    cvt_all_kernel<<<12 * M1 / 8 / 256, 256>>>(w_qkv, w_o, w_fc1, w_fc2, wc);

    // 1. LN1 -> fp16
    ln_kernel<<<MM, 256>>>(x, ln1_g, ln1_b, xn);
    // 2. QKV projection -> fp16
    gemm_mma<0><<<dim3(E3 / BN, MM / BM), 512, GEMM_SMEM>>>(xn, wc_qkv, b_qkv, nullptr,
                                                            qkvb, MM, E3, EE);
    // 3. FP16 tensor-core attention -> fp16
    attn_tc<<<dim3(SS / 128, BB * HH), 256, ATT_SMEM>>>(qkvb, td, attnb);
    // 4. O projection + residual -> fp32
    gemm_mma<1><<<dim3(EE / BN, MM / BM), 512, GEMM_SMEM>>>(attnb, wc_o, b_o, x,
                                                            x2, MM, EE, EE);
    // 5. LN2 -> fp16
    ln_kernel<<<MM, 256>>>(x2, ln2_g, ln2_b, xn);
    // 6. FC1 + GELU -> fp16
    gemm_mma<2><<<dim3(FFD / BN, MM / BM), 512, GEMM_SMEM>>>(xn, wc_fc1, b_fc1, nullptr,
                                                             fc1b, MM, FFD, EE);
    // 7. FC2 + residual -> fp32 out
    gemm_mma<1><<<dim3(EE / BN, MM / BM), 512, GEMM_SMEM>>>(fc1b, wc_fc2, b_fc2, x2,
                                                            out, MM, EE, FFD);
}

// round 16
// speedup vs baseline: 1.0264x; 1.0264x over previous
#include <cuda_runtime.h>
#include <cuda_fp16.h>
#include <math.h>
#include <stdint.h>

// Problem constants
#define BB 4
#define SS 2048
#define EE 1024
#define HH 16
#define DH 64
#define FFD 4096
#define MM (BB * SS)          // 8192 tokens
#define E3 (3 * EE)           // 3072

// ---------------------------------------------------------------------------
// Scratch buffers (device globals; allocation-free)
// ---------------------------------------------------------------------------
__device__ __align__(128) __half g_xn[(size_t)MM * EE];
__device__ __align__(128) __half g_qkv[(size_t)MM * E3];
__device__ __align__(128) __half g_attn[(size_t)MM * EE];
__device__ __align__(128) float  g_x2[(size_t)MM * EE];
__device__ __align__(128) __half g_fc1[(size_t)MM * FFD];
__device__ __align__(128) __half g_wc[(size_t)12 * 1024 * 1024];

// ---------------------------------------------------------------------------
// Helpers
// ---------------------------------------------------------------------------
__device__ __forceinline__ uint32_t smem_u32(const void* p) {
    uint32_t a;
    asm("{ .reg .u64 t; cvta.to.shared.u64 t, %1; cvt.u32.u64 %0, t; }"
        : "=r"(a) : "l"(p));
    return a;
}
__device__ __forceinline__ void cp16(uint32_t s, const void* g) {
    asm volatile("cp.async.cg.shared.global [%0], [%1], 16;" :: "r"(s), "l"(g));
}
#define CP_COMMIT asm volatile("cp.async.commit_group;" ::: "memory")
#define CP_WAIT1  asm volatile("cp.async.wait_group 1;" ::: "memory")
#define CP_WAIT0  asm volatile("cp.async.wait_group 0;" ::: "memory")

__device__ __forceinline__ void mmah(float c[4], const uint32_t a[4],
                                     uint32_t b0, uint32_t b1) {
    asm volatile(
        "mma.sync.aligned.m16n8k16.row.col.f32.f16.f16.f32 "
        "{%0,%1,%2,%3}, {%4,%5,%6,%7}, {%8,%9}, {%0,%1,%2,%3};"
        : "+f"(c[0]), "+f"(c[1]), "+f"(c[2]), "+f"(c[3])
        : "r"(a[0]), "r"(a[1]), "r"(a[2]), "r"(a[3]), "r"(b0), "r"(b1));
}
#define LDSM4(r, addr) \
    asm volatile("ldmatrix.sync.aligned.m8n8.x4.shared.b16 {%0,%1,%2,%3}, [%4];" \
        : "=r"((r)[0]), "=r"((r)[1]), "=r"((r)[2]), "=r"((r)[3]) : "r"(addr))
#define LDSM4T(r, addr) \
    asm volatile("ldmatrix.sync.aligned.m8n8.x4.trans.shared.b16 {%0,%1,%2,%3}, [%4];" \
        : "=r"((r)[0]), "=r"((r)[1]), "=r"((r)[2]), "=r"((r)[3]) : "r"(addr))

__device__ __forceinline__ uint32_t packf2(float lo, float hi) {
    __half2 h = __floats2half2_rn(lo, hi);
    return *(uint32_t*)&h;
}

// ---------------------------------------------------------------------------
// Fused weight convert fp32 -> fp16 (all 4 weight matrices, one launch)
// ---------------------------------------------------------------------------
#define M1 (1024 * 1024)
__global__ void __launch_bounds__(256) cvt_all_kernel(
    const float* __restrict__ w_qkv, const float* __restrict__ w_o,
    const float* __restrict__ w_fc1, const float* __restrict__ w_fc2,
    __half* __restrict__ out) {
    int i = (blockIdx.x * 256 + threadIdx.x) * 8;
    const float* src;
    int ofs;
    if (i < 3 * M1)       { src = w_qkv; ofs = i; }
    else if (i < 4 * M1)  { src = w_o;   ofs = i - 3 * M1; }
    else if (i < 8 * M1)  { src = w_fc1; ofs = i - 4 * M1; }
    else                  { src = w_fc2; ofs = i - 8 * M1; }
    float4 v0 = *(const float4*)(src + ofs);
    float4 v1 = *(const float4*)(src + ofs + 4);
    __half2 h[4];
    h[0] = __floats2half2_rn(v0.x, v0.y);
    h[1] = __floats2half2_rn(v0.z, v0.w);
    h[2] = __floats2half2_rn(v1.x, v1.y);
    h[3] = __floats2half2_rn(v1.z, v1.w);
    *(uint2*)(out + i)     = make_uint2(*(uint32_t*)&h[0], *(uint32_t*)&h[1]);
    *(uint2*)(out + i + 4) = make_uint2(*(uint32_t*)&h[2], *(uint32_t*)&h[3]);
}

// ---------------------------------------------------------------------------
// FP16 mma.sync GEMM NT (R14 proven config): CTA 128x128x64, 8 warps (4Mx2N),
// warp 32x64, 3-stage cp.async ring, one sync per K-iter, 2 CTAs/SM.
//   EPI 0: + bias -> half   EPI 1: + bias + residual -> float
//   EPI 2: + bias, exact GELU -> half
// ---------------------------------------------------------------------------
#define BM 128
#define BN 128
#define BK 64
#define SROWB 144
#define ASTGB (BM * SROWB)
#define STGB (2 * ASTGB)
#define NSTG 3
#define GEMM_SMEM (NSTG * STGB)

template <int EPI>
__global__ void __launch_bounds__(256, 2) gemm_mma(
    const __half* __restrict__ A, const __half* __restrict__ W,
    const float* __restrict__ bias, const float* __restrict__ res,
    void* __restrict__ Cv, int M, int N, int K)
{
    extern __shared__ char smemraw[];
    const int tid = threadIdx.x;
    const int bm = blockIdx.y * BM;
    const int bn = blockIdx.x * BN;
    const uint32_t sbase = smem_u32(smemraw);

    const int w = tid >> 5, lane = tid & 31;
    const int t = lane & 3;
    const int g = lane >> 2;
    const int wm = (w & 3) * 32;
    const int wn = (w >> 2) * 64;

    const uint32_t aLd = (wm + (lane & 15)) * SROWB + ((lane >> 4) << 4);
    const uint32_t bLd = (wn + (lane & 7) + ((lane >> 4) << 3)) * SROWB
                         + (((lane >> 3) & 1) << 4);

    const __half* Ag = A + (size_t)bm * K;
    const __half* Wg = W + (size_t)bn * K;

    float acc[2][8][4];
    #pragma unroll
    for (int mi = 0; mi < 2; mi++)
        #pragma unroll
        for (int ni = 0; ni < 8; ni++)
            #pragma unroll
            for (int j = 0; j < 4; j++) acc[mi][ni][j] = 0.0f;

    auto load_tile = [&](int stg, int kt) {
        const uint32_t dA = sbase + stg * STGB;
        const uint32_t dB = dA + ASTGB;
        const int kofs = kt * BK;
        #pragma unroll
        for (int i = 0; i < 4; i++) {
            int chunk = tid + i * 256;
            int r = chunk >> 3, c = chunk & 7;
            cp16(dA + r * SROWB + c * 16, Ag + (size_t)r * K + kofs + c * 8);
        }
        #pragma unroll
        for (int i = 0; i < 4; i++) {
            int chunk = tid + i * 256;
            int r = chunk >> 3, c = chunk & 7;
            cp16(dB + r * SROWB + c * 16, Wg + (size_t)r * K + kofs + c * 8);
        }
    };

    const int nk = K / BK;
    load_tile(0, 0); CP_COMMIT;
    load_tile(1, 1); CP_COMMIT;

    for (int kt = 0; kt < nk; kt++) {
        const int s = kt % NSTG;
        CP_WAIT1;
        __syncthreads();
        const int nxt = kt + 2;
        if (nxt < nk) load_tile(nxt % NSTG, nxt);
        CP_COMMIT;

        const uint32_t aBase = sbase + s * STGB + aLd;
        const uint32_t bBase = sbase + s * STGB + ASTGB + bLd;

        #pragma unroll
        for (int ks = 0; ks < 4; ks++) {
            const uint32_t ko = ks * 32;
            uint32_t a0[4], a1[4], bq[4][4];
            LDSM4(a0, aBase + ko);
            LDSM4(a1, aBase + 16 * SROWB + ko);
            #pragma unroll
            for (int p = 0; p < 4; p++)
                LDSM4(bq[p], bBase + p * 16 * SROWB + ko);
            #pragma unroll
            for (int p = 0; p < 4; p++) {
                mmah(acc[0][2 * p],     a0, bq[p][0], bq[p][1]);
                mmah(acc[0][2 * p + 1], a0, bq[p][2], bq[p][3]);
                mmah(acc[1][2 * p],     a1, bq[p][0], bq[p][1]);
                mmah(acc[1][2 * p + 1], a1, bq[p][2], bq[p][3]);
            }
        }
    }

    float bb[8][2];
    #pragma unroll
    for (int ni = 0; ni < 8; ni++) {
        int col = bn + wn + ni * 8 + t * 2;
        bb[ni][0] = __ldg(bias + col);
        bb[ni][1] = __ldg(bias + col + 1);
    }
    #pragma unroll
    for (int mi = 0; mi < 2; mi++) {
        #pragma unroll
        for (int h = 0; h < 2; h++) {
            const int row = bm + wm + mi * 16 + g + h * 8;
            #pragma unroll
            for (int ni = 0; ni < 8; ni++) {
                const int col = bn + wn + ni * 8 + t * 2;
                float o0 = acc[mi][ni][h * 2 + 0] + bb[ni][0];
                float o1 = acc[mi][ni][h * 2 + 1] + bb[ni][1];
                if (EPI == 0) {
                    *(__half2*)((__half*)Cv + (size_t)row * N + col) =
                        __floats2half2_rn(o0, o1);
                } else if (EPI == 1) {
                    const float2 rv = *(const float2*)(res + (size_t)row * N + col);
                    *(float2*)((float*)Cv + (size_t)row * N + col) =
                        make_float2(o0 + rv.x, o1 + rv.y);
                } else {
                    o0 = 0.5f * o0 * (1.0f + erff(o0 * 0.70710678118654752f));
                    o1 = 0.5f * o1 * (1.0f + erff(o1 * 0.70710678118654752f));
                    *(__half2*)((__half*)Cv + (size_t)row * N + col) =
                        __floats2half2_rn(o0, o1);
                }
            }
        }
    }
}

// ---------------------------------------------------------------------------
// LayerNorm: one block per token row of 1024; fp16 output
// ---------------------------------------------------------------------------
__global__ void __launch_bounds__(256) ln_kernel(const float* __restrict__ x,
                                                 const float* __restrict__ g,
                                                 const float* __restrict__ b,
                                                 __half* __restrict__ out) {
    int row = blockIdx.x;
    const float4* xr = (const float4*)(x + (size_t)row * EE);
    float4 v = xr[threadIdx.x];
    float s  = v.x + v.y + v.z + v.w;
    float sq = v.x * v.x + v.y * v.y + v.z * v.z + v.w * v.w;
    #pragma unroll
    for (int o = 16; o; o >>= 1) {
        s  += __shfl_xor_sync(0xffffffffu, s,  o);
        sq += __shfl_xor_sync(0xffffffffu, sq, o);
    }
    __shared__ float ss[8], ssq[8];
    int w = threadIdx.x >> 5, ln = threadIdx.x & 31;
    if (ln == 0) { ss[w] = s; ssq[w] = sq; }
    __syncthreads();
    if (w == 0) {
        s  = (ln < 8) ? ss[ln]  : 0.0f;
        sq = (ln < 8) ? ssq[ln] : 0.0f;
        #pragma unroll
        for (int o = 4; o; o >>= 1) {
            s  += __shfl_xor_sync(0xffffffffu, s,  o);
            sq += __shfl_xor_sync(0xffffffffu, sq, o);
        }
        if (ln == 0) { ss[0] = s; ssq[0] = sq; }
    }
    __syncthreads();
    float mean = ss[0] * (1.0f / EE);
    float var  = ssq[0] * (1.0f / EE) - mean * mean;
    float rstd = rsqrtf(var + 1e-5f);
    int c = threadIdx.x * 4;
    float4 gg = *(const float4*)(g + c);
    float4 bb = *(const float4*)(b + c);
    __half2 h0 = __floats2half2_rn((v.x - mean) * rstd * gg.x + bb.x,
                                   (v.y - mean) * rstd * gg.y + bb.y);
    __half2 h1 = __floats2half2_rn((v.z - mean) * rstd * gg.z + bb.z,
                                   (v.w - mean) * rstd * gg.w + bb.w);
    *(uint2*)(out + (size_t)row * EE + c) =
        make_uint2(*(uint32_t*)&h0, *(uint32_t*)&h1);
}

// ---------------------------------------------------------------------------
// FP16 tensor-core flash attention; register-resident P; LUT periodic mask;
// double-buffered cp.async K/V; reversed qb order; guarded O-rescale.
// ---------------------------------------------------------------------------
#define AS2 72
#define ASB (AS2 * 2)
#define KVB (128 * ASB)
#define ATT_SMEM ((128 + 256) * ASB + 256)

__global__ void __launch_bounds__(256, 2) attn_tc(const __half* __restrict__ qkv,
                                                  const int* __restrict__ tdp,
                                                  __half* __restrict__ out) {
    extern __shared__ char smemraw[];
    __half* Qs  = (__half*)smemraw;
    __half* KV0 = Qs + 128 * AS2;
    __half* kmaskS = KV0 + 2 * 128 * AS2;

    const int qb = gridDim.x - 1 - blockIdx.x;   // longest tiles first
    const int bh = blockIdx.y;
    const int b = bh >> 4, h = bh & 15;
    const int TD = tdp[0];
    const int tid = threadIdx.x, w = tid >> 5, lane = tid & 31;
    const int g = lane >> 2, t = lane & 3;

    const size_t base = (size_t)b * SS * E3 + (size_t)h * DH;
    const uint32_t kvBase = smem_u32(KV0);

    const uint32_t qLd = smem_u32(Qs) +
        (w * 16 + (lane & 15)) * ASB + ((lane >> 4) << 4);
    const uint32_t kLd0 = kvBase +
        ((lane & 7) + ((lane >> 4) << 3)) * ASB + (((lane >> 3) & 1) << 4);
    const uint32_t vLd0 = kvBase + 64 * ASB +
        (lane & 15) * ASB + ((lane >> 4) << 4);

    for (int i = tid; i < 128 * 8; i += 256) {
        int r = i >> 3, c = (i & 7) * 8;
        *(uint4*)(Qs + r * AS2 + c) =
            *(const uint4*)(qkv + base + (size_t)(qb * 128 + r) * E3 + c);
    }

    auto load_kv = [&](int kb, int buf) {
        const uint32_t dst = kvBase + buf * KVB;
        #pragma unroll
        for (int i = 0; i < 2; i++) {
            int chunk = tid + i * 256;
            int r = chunk >> 3, cB = (chunk & 7) << 4;
            size_t off = base + (size_t)(kb * 64 + r) * E3 + (cB >> 1);
            cp16(dst + r * ASB + cB,            qkv + off + EE);
            cp16(dst + 64 * ASB + r * ASB + cB, qkv + off + 2 * EE);
        }
        if (tid < 64) {
            int col = kb * 64 + tid;
            kmaskS[buf * 64 + tid] =
                ((col % TD) == TD - 1) ? __float2half(0.0f) : __float2half(1.0f);
        }
    };

    float m0 = -1e30f, m1 = -1e30f, l0 = 0.0f, l1 = 0.0f;
    float o[8][4];
    #pragma unroll
    for (int ni = 0; ni < 8; ni++)
        #pragma unroll
        for (int j = 0; j < 4; j++) o[ni][j] = 0.0f;

    const int ig0 = qb * 128 + w * 16 + g;
    const int ig1 = ig0 + 8;
    const int nkt = 2 * qb + 2;

    load_kv(0, 0); CP_COMMIT;

    for (int kb = 0; kb < nkt; kb++) {
        const int buf = kb & 1;
        CP_WAIT0;
        __syncthreads();
        if (kb + 1 < nkt) load_kv(kb + 1, buf ^ 1);
        CP_COMMIT;

        const uint32_t kLd = kLd0 + buf * KVB;
        const uint32_t vLd = vLd0 + buf * KVB;

        float s[8][4];
        #pragma unroll
        for (int ni = 0; ni < 8; ni++)
            #pragma unroll
            for (int j = 0; j < 4; j++) s[ni][j] = 0.0f;

        #pragma unroll
        for (int ks = 0; ks < 4; ks++) {
            const uint32_t ko = ks * 32;
            uint32_t aq[4];
            LDSM4(aq, qLd + ko);
            #pragma unroll
            for (int p = 0; p < 4; p++) {
                uint32_t bk[4];
                LDSM4(bk, kLd + p * 16 * ASB + ko);
                mmah(s[2 * p],     aq, bk[0], bk[1]);
                mmah(s[2 * p + 1], aq, bk[2], bk[3]);
            }
        }

        if (kb >= nkt - 2) {
            const int colb = kb * 64 + t * 2;
            #pragma unroll
            for (int ni = 0; ni < 8; ni++) {
                #pragma unroll
                for (int j = 0; j < 2; j++) {
                    const int col = colb + ni * 8 + j;
                    s[ni][j]     = (col > ig0) ? -1e30f : s[ni][j] * 0.125f;
                    s[ni][2 + j] = (col > ig1) ? -1e30f : s[ni][2 + j] * 0.125f;
                }
            }
        } else {
            #pragma unroll
            for (int ni = 0; ni < 8; ni++)
                #pragma unroll
                for (int j = 0; j < 4; j++) s[ni][j] *= 0.125f;
        }

        float rm0 = -1e30f, rm1 = -1e30f;
        #pragma unroll
        for (int ni = 0; ni < 8; ni++) {
            rm0 = fmaxf(rm0, fmaxf(s[ni][0], s[ni][1]));
            rm1 = fmaxf(rm1, fmaxf(s[ni][2], s[ni][3]));
        }
        #pragma unroll
        for (int ofs = 1; ofs < 4; ofs <<= 1) {
            rm0 = fmaxf(rm0, __shfl_xor_sync(0xffffffffu, rm0, ofs));
            rm1 = fmaxf(rm1, __shfl_xor_sync(0xffffffffu, rm1, ofs));
        }
        const float nm0 = fmaxf(m0, rm0), nm1 = fmaxf(m1, rm1);
        const float a0 = __expf(m0 - nm0), a1 = __expf(m1 - nm1);

        const __half2* km = (const __half2*)(kmaskS + buf * 64) + t;
        float rs0 = 0.0f, rs1 = 0.0f;
        #pragma unroll
        for (int ni = 0; ni < 8; ni++) {
            const float2 mk = __half22float2(km[ni * 4]);
            s[ni][0] = __expf(s[ni][0] - nm0) * mk.x;
            s[ni][1] = __expf(s[ni][1] - nm0) * mk.y;
            s[ni][2] = __expf(s[ni][2] - nm1) * mk.x;
            s[ni][3] = __expf(s[ni][3] - nm1) * mk.y;
            rs0 += s[ni][0] + s[ni][1];
            rs1 += s[ni][2] + s[ni][3];
        }
        #pragma unroll
        for (int ofs = 1; ofs < 4; ofs <<= 1) {
            rs0 += __shfl_xor_sync(0xffffffffu, rs0, ofs);
            rs1 += __shfl_xor_sync(0xffffffffu, rs1, ofs);
        }
        l0 = l0 * a0 + rs0;
        l1 = l1 * a1 + rs1;
        if (nm0 > m0 || nm1 > m1) {
            #pragma unroll
            for (int ni = 0; ni < 8; ni++) {
                o[ni][0] *= a0; o[ni][1] *= a0;
                o[ni][2] *= a1; o[ni][3] *= a1;
            }
        }
        m0 = nm0; m1 = nm1;

        #pragma unroll
        for (int ks = 0; ks < 4; ks++) {
            uint32_t a[4];
            a[0] = packf2(s[2 * ks][0],     s[2 * ks][1]);
            a[1] = packf2(s[2 * ks][2],     s[2 * ks][3]);
            a[2] = packf2(s[2 * ks + 1][0], s[2 * ks + 1][1]);
            a[3] = packf2(s[2 * ks + 1][2], s[2 * ks + 1][3]);
            const uint32_t vBase = vLd + ks * 16 * ASB;
            #pragma unroll
            for (int db = 0; db < 4; db++) {
                uint32_t bv[4];
                LDSM4T(bv, vBase + db * 32);
                mmah(o[2 * db],     a, bv[0], bv[1]);
                mmah(o[2 * db + 1], a, bv[2], bv[3]);
            }
        }
    }

    const float inv0 = 1.0f / l0, inv1 = 1.0f / l1;
    const size_t r0o = ((size_t)(b * SS + qb * 128 + w * 16 + g)) * EE + h * DH;
    const size_t r1o = r0o + 8 * EE;
    #pragma unroll
    for (int ni = 0; ni < 8; ni++) {
        const int c = ni * 8 + t * 2;
        *(__half2*)(out + r0o + c) = __floats2half2_rn(o[ni][0] * inv0, o[ni][1] * inv0);
        *(__half2*)(out + r1o + c) = __floats2half2_rn(o[ni][2] * inv1, o[ni][3] * inv1);
    }
}

// ---------------------------------------------------------------------------
// Launch
// ---------------------------------------------------------------------------
extern "C" void kernel_launch(void* const* d_in, const int* in_sizes, int n_in,
                              void* d_out, int out_size) {
    const float* x      = (const float*)d_in[0];
    const int*   td     = (const int*)d_in[1];
    const float* ln1_g  = (const float*)d_in[2];
    const float* ln1_b  = (const float*)d_in[3];
    const float* ln2_g  = (const float*)d_in[4];
    const float* ln2_b  = (const float*)d_in[5];
    const float* w_qkv  = (const float*)d_in[6];
    const float* b_qkv  = (const float*)d_in[7];
    const float* w_o    = (const float*)d_in[8];
    const float* b_o    = (const float*)d_in[9];
    const float* w_fc1  = (const float*)d_in[10];
    const float* b_fc1  = (const float*)d_in[11];
    const float* w_fc2  = (const float*)d_in[12];
    const float* b_fc2  = (const float*)d_in[13];
    float* out = (float*)d_out;

    __half *xn, *qkvb, *attnb, *fc1b, *wc;
    float *x2;
    cudaGetSymbolAddress((void**)&xn,    g_xn);
    cudaGetSymbolAddress((void**)&qkvb,  g_qkv);
    cudaGetSymbolAddress((void**)&attnb, g_attn);
    cudaGetSymbolAddress((void**)&x2,    g_x2);
    cudaGetSymbolAddress((void**)&fc1b,  g_fc1);
    cudaGetSymbolAddress((void**)&wc,    g_wc);

    __half* wc_qkv = wc;
    __half* wc_o   = wc + (size_t)3 * M1;
    __half* wc_fc1 = wc + (size_t)4 * M1;
    __half* wc_fc2 = wc + (size_t)8 * M1;

    cudaFuncSetAttribute(gemm_mma<0>, cudaFuncAttributeMaxDynamicSharedMemorySize, GEMM_SMEM);
    cudaFuncSetAttribute(gemm_mma<1>, cudaFuncAttributeMaxDynamicSharedMemorySize, GEMM_SMEM);
    cudaFuncSetAttribute(gemm_mma<2>, cudaFuncAttributeMaxDynamicSharedMemorySize, GEMM_SMEM);
    cudaFuncSetAttribute(attn_tc, cudaFuncAttributeMaxDynamicSharedMemorySize, ATT_SMEM);

    // 0. Convert all weights to fp16, one launch
    cvt_all_kernel<<<12 * M1 / 8 / 256, 256>>>(w_qkv, w_o, w_fc1, w_fc2, wc);

    // 1. LN1 -> fp16
    ln_kernel<<<MM, 256>>>(x, ln1_g, ln1_b, xn);
    // 2. QKV projection -> fp16
    gemm_mma<0><<<dim3(E3 / BN, MM / BM), 256, GEMM_SMEM>>>(xn, wc_qkv, b_qkv, nullptr,
                                                            qkvb, MM, E3, EE);
    // 3. FP16 tensor-core attention -> fp16
    attn_tc<<<dim3(SS / 128, BB * HH), 256, ATT_SMEM>>>(qkvb, td, attnb);
    // 4. O projection + residual -> fp32
    gemm_mma<1><<<dim3(EE / BN, MM / BM), 256, GEMM_SMEM>>>(attnb, wc_o, b_o, x,
                                                            x2, MM, EE, EE);
    // 5. LN2 -> fp16
    ln_kernel<<<MM, 256>>>(x2, ln2_g, ln2_b, xn);
    // 6. FC1 + GELU -> fp16
    gemm_mma<2><<<dim3(FFD / BN, MM / BM), 256, GEMM_SMEM>>>(xn, wc_fc1, b_fc1, nullptr,
                                                             fc1b, MM, FFD, EE);
    // 7. FC2 + residual -> fp32 out
    gemm_mma<1><<<dim3(EE / BN, MM / BM), 256, GEMM_SMEM>>>(fc1b, wc_fc2, b_fc2, x2,
                                                            out, MM, EE, FFD);
}

// round 17
// speedup vs baseline: 1.0311x; 1.0046x over previous
#include <cuda_runtime.h>
#include <cuda_fp16.h>
#include <math.h>
#include <stdint.h>

// Problem constants
#define BB 4
#define SS 2048
#define EE 1024
#define HH 16
#define DH 64
#define FFD 4096
#define MM (BB * SS)          // 8192 tokens
#define E3 (3 * EE)           // 3072

// ---------------------------------------------------------------------------
// Scratch buffers (device globals; allocation-free)
// ---------------------------------------------------------------------------
__device__ __align__(128) __half g_xn[(size_t)MM * EE];
__device__ __align__(128) __half g_qkv[(size_t)MM * E3];
__device__ __align__(128) __half g_attn[(size_t)MM * EE];
__device__ __align__(128) float  g_x2[(size_t)MM * EE];
__device__ __align__(128) __half g_fc1[(size_t)MM * FFD];
__device__ __align__(128) __half g_wc[(size_t)12 * 1024 * 1024];

// ---------------------------------------------------------------------------
// Helpers
// ---------------------------------------------------------------------------
__device__ __forceinline__ uint32_t smem_u32(const void* p) {
    uint32_t a;
    asm("{ .reg .u64 t; cvta.to.shared.u64 t, %1; cvt.u32.u64 %0, t; }"
        : "=r"(a) : "l"(p));
    return a;
}
__device__ __forceinline__ void cp16(uint32_t s, const void* g) {
    asm volatile("cp.async.cg.shared.global [%0], [%1], 16;" :: "r"(s), "l"(g));
}
#define CP_COMMIT asm volatile("cp.async.commit_group;" ::: "memory")
#define CP_WAIT1  asm volatile("cp.async.wait_group 1;" ::: "memory")
#define CP_WAIT0  asm volatile("cp.async.wait_group 0;" ::: "memory")

__device__ __forceinline__ void mmah(float c[4], const uint32_t a[4],
                                     uint32_t b0, uint32_t b1) {
    asm volatile(
        "mma.sync.aligned.m16n8k16.row.col.f32.f16.f16.f32 "
        "{%0,%1,%2,%3}, {%4,%5,%6,%7}, {%8,%9}, {%0,%1,%2,%3};"
        : "+f"(c[0]), "+f"(c[1]), "+f"(c[2]), "+f"(c[3])
        : "r"(a[0]), "r"(a[1]), "r"(a[2]), "r"(a[3]), "r"(b0), "r"(b1));
}
#define LDSM4(r, addr) \
    asm volatile("ldmatrix.sync.aligned.m8n8.x4.shared.b16 {%0,%1,%2,%3}, [%4];" \
        : "=r"((r)[0]), "=r"((r)[1]), "=r"((r)[2]), "=r"((r)[3]) : "r"(addr))
#define LDSM4T(r, addr) \
    asm volatile("ldmatrix.sync.aligned.m8n8.x4.trans.shared.b16 {%0,%1,%2,%3}, [%4];" \
        : "=r"((r)[0]), "=r"((r)[1]), "=r"((r)[2]), "=r"((r)[3]) : "r"(addr))

// ---------------------------------------------------------------------------
// Fused weight convert fp32 -> fp16 (all 4 weight matrices, one launch)
// ---------------------------------------------------------------------------
#define M1 (1024 * 1024)
__global__ void __launch_bounds__(256) cvt_all_kernel(
    const float* __restrict__ w_qkv, const float* __restrict__ w_o,
    const float* __restrict__ w_fc1, const float* __restrict__ w_fc2,
    __half* __restrict__ out) {
    int i = (blockIdx.x * 256 + threadIdx.x) * 8;
    const float* src;
    int ofs;
    if (i < 3 * M1)       { src = w_qkv; ofs = i; }
    else if (i < 4 * M1)  { src = w_o;   ofs = i - 3 * M1; }
    else if (i < 8 * M1)  { src = w_fc1; ofs = i - 4 * M1; }
    else                  { src = w_fc2; ofs = i - 8 * M1; }
    float4 v0 = *(const float4*)(src + ofs);
    float4 v1 = *(const float4*)(src + ofs + 4);
    __half2 h[4];
    h[0] = __floats2half2_rn(v0.x, v0.y);
    h[1] = __floats2half2_rn(v0.z, v0.w);
    h[2] = __floats2half2_rn(v1.x, v1.y);
    h[3] = __floats2half2_rn(v1.z, v1.w);
    *(uint2*)(out + i)     = make_uint2(*(uint32_t*)&h[0], *(uint32_t*)&h[1]);
    *(uint2*)(out + i + 4) = make_uint2(*(uint32_t*)&h[2], *(uint32_t*)&h[3]);
}

// ---------------------------------------------------------------------------
// FP16 mma.sync GEMM NT (proven config): CTA 128x128x64, 8 warps (4Mx2N),
// warp 32x64, 3-stage cp.async ring, one sync per K-iter, 2 CTAs/SM.
//   EPI 0: + bias -> half   EPI 1: + bias + residual -> float
//   EPI 2: + bias, exact GELU -> half
// ---------------------------------------------------------------------------
#define BM 128
#define BN 128
#define BK 64
#define SROWB 144
#define ASTGB (BM * SROWB)
#define STGB (2 * ASTGB)
#define NSTG 3
#define GEMM_SMEM (NSTG * STGB)

template <int EPI>
__global__ void __launch_bounds__(256, 2) gemm_mma(
    const __half* __restrict__ A, const __half* __restrict__ W,
    const float* __restrict__ bias, const float* __restrict__ res,
    void* __restrict__ Cv, int M, int N, int K)
{
    extern __shared__ char smemraw[];
    const int tid = threadIdx.x;
    const int bm = blockIdx.y * BM;
    const int bn = blockIdx.x * BN;
    const uint32_t sbase = smem_u32(smemraw);

    const int w = tid >> 5, lane = tid & 31;
    const int t = lane & 3;
    const int g = lane >> 2;
    const int wm = (w & 3) * 32;
    const int wn = (w >> 2) * 64;

    const uint32_t aLd = (wm + (lane & 15)) * SROWB + ((lane >> 4) << 4);
    const uint32_t bLd = (wn + (lane & 7) + ((lane >> 4) << 3)) * SROWB
                         + (((lane >> 3) & 1) << 4);

    const __half* Ag = A + (size_t)bm * K;
    const __half* Wg = W + (size_t)bn * K;

    float acc[2][8][4];
    #pragma unroll
    for (int mi = 0; mi < 2; mi++)
        #pragma unroll
        for (int ni = 0; ni < 8; ni++)
            #pragma unroll
            for (int j = 0; j < 4; j++) acc[mi][ni][j] = 0.0f;

    auto load_tile = [&](int stg, int kt) {
        const uint32_t dA = sbase + stg * STGB;
        const uint32_t dB = dA + ASTGB;
        const int kofs = kt * BK;
        #pragma unroll
        for (int i = 0; i < 4; i++) {
            int chunk = tid + i * 256;
            int r = chunk >> 3, c = chunk & 7;
            cp16(dA + r * SROWB + c * 16, Ag + (size_t)r * K + kofs + c * 8);
        }
        #pragma unroll
        for (int i = 0; i < 4; i++) {
            int chunk = tid + i * 256;
            int r = chunk >> 3, c = chunk & 7;
            cp16(dB + r * SROWB + c * 16, Wg + (size_t)r * K + kofs + c * 8);
        }
    };

    const int nk = K / BK;
    load_tile(0, 0); CP_COMMIT;
    load_tile(1, 1); CP_COMMIT;

    for (int kt = 0; kt < nk; kt++) {
        const int s = kt % NSTG;
        CP_WAIT1;
        __syncthreads();
        const int nxt = kt + 2;
        if (nxt < nk) load_tile(nxt % NSTG, nxt);
        CP_COMMIT;

        const uint32_t aBase = sbase + s * STGB + aLd;
        const uint32_t bBase = sbase + s * STGB + ASTGB + bLd;

        #pragma unroll
        for (int ks = 0; ks < 4; ks++) {
            const uint32_t ko = ks * 32;
            uint32_t a0[4], a1[4], bq[4][4];
            LDSM4(a0, aBase + ko);
            LDSM4(a1, aBase + 16 * SROWB + ko);
            #pragma unroll
            for (int p = 0; p < 4; p++)
                LDSM4(bq[p], bBase + p * 16 * SROWB + ko);
            #pragma unroll
            for (int p = 0; p < 4; p++) {
                mmah(acc[0][2 * p],     a0, bq[p][0], bq[p][1]);
                mmah(acc[0][2 * p + 1], a0, bq[p][2], bq[p][3]);
                mmah(acc[1][2 * p],     a1, bq[p][0], bq[p][1]);
                mmah(acc[1][2 * p + 1], a1, bq[p][2], bq[p][3]);
            }
        }
    }

    float bb[8][2];
    #pragma unroll
    for (int ni = 0; ni < 8; ni++) {
        int col = bn + wn + ni * 8 + t * 2;
        bb[ni][0] = __ldg(bias + col);
        bb[ni][1] = __ldg(bias + col + 1);
    }
    #pragma unroll
    for (int mi = 0; mi < 2; mi++) {
        #pragma unroll
        for (int h = 0; h < 2; h++) {
            const int row = bm + wm + mi * 16 + g + h * 8;
            #pragma unroll
            for (int ni = 0; ni < 8; ni++) {
                const int col = bn + wn + ni * 8 + t * 2;
                float o0 = acc[mi][ni][h * 2 + 0] + bb[ni][0];
                float o1 = acc[mi][ni][h * 2 + 1] + bb[ni][1];
                if (EPI == 0) {
                    *(__half2*)((__half*)Cv + (size_t)row * N + col) =
                        __floats2half2_rn(o0, o1);
                } else if (EPI == 1) {
                    const float2 rv = *(const float2*)(res + (size_t)row * N + col);
                    *(float2*)((float*)Cv + (size_t)row * N + col) =
                        make_float2(o0 + rv.x, o1 + rv.y);
                } else {
                    o0 = 0.5f * o0 * (1.0f + erff(o0 * 0.70710678118654752f));
                    o1 = 0.5f * o1 * (1.0f + erff(o1 * 0.70710678118654752f));
                    *(__half2*)((__half*)Cv + (size_t)row * N + col) =
                        __floats2half2_rn(o0, o1);
                }
            }
        }
    }
}

// ---------------------------------------------------------------------------
// LayerNorm: one block per token row of 1024; fp16 output
// ---------------------------------------------------------------------------
__global__ void __launch_bounds__(256) ln_kernel(const float* __restrict__ x,
                                                 const float* __restrict__ g,
                                                 const float* __restrict__ b,
                                                 __half* __restrict__ out) {
    int row = blockIdx.x;
    const float4* xr = (const float4*)(x + (size_t)row * EE);
    float4 v = xr[threadIdx.x];
    float s  = v.x + v.y + v.z + v.w;
    float sq = v.x * v.x + v.y * v.y + v.z * v.z + v.w * v.w;
    #pragma unroll
    for (int o = 16; o; o >>= 1) {
        s  += __shfl_xor_sync(0xffffffffu, s,  o);
        sq += __shfl_xor_sync(0xffffffffu, sq, o);
    }
    __shared__ float ss[8], ssq[8];
    int w = threadIdx.x >> 5, ln = threadIdx.x & 31;
    if (ln == 0) { ss[w] = s; ssq[w] = sq; }
    __syncthreads();
    if (w == 0) {
        s  = (ln < 8) ? ss[ln]  : 0.0f;
        sq = (ln < 8) ? ssq[ln] : 0.0f;
        #pragma unroll
        for (int o = 4; o; o >>= 1) {
            s  += __shfl_xor_sync(0xffffffffu, s,  o);
            sq += __shfl_xor_sync(0xffffffffu, sq, o);
        }
        if (ln == 0) { ss[0] = s; ssq[0] = sq; }
    }
    __syncthreads();
    float mean = ss[0] * (1.0f / EE);
    float var  = ssq[0] * (1.0f / EE) - mean * mean;
    float rstd = rsqrtf(var + 1e-5f);
    int c = threadIdx.x * 4;
    float4 gg = *(const float4*)(g + c);
    float4 bb = *(const float4*)(b + c);
    __half2 h0 = __floats2half2_rn((v.x - mean) * rstd * gg.x + bb.x,
                                   (v.y - mean) * rstd * gg.y + bb.y);
    __half2 h1 = __floats2half2_rn((v.z - mean) * rstd * gg.z + bb.z,
                                   (v.w - mean) * rstd * gg.w + bb.w);
    *(uint2*)(out + (size_t)row * EE + c) =
        make_uint2(*(uint32_t*)&h0, *(uint32_t*)&h1);
}

// ---------------------------------------------------------------------------
// FP16 tensor-core flash attention; register-resident P; LUT periodic mask;
// double-buffered cp.async K/V; base-2 softmax with h2exp2 (fp16 P direct).
// Scores scaled by 0.125*log2(e); all max/rescale math in log2 units.
// ---------------------------------------------------------------------------
#define AS2 72
#define ASB (AS2 * 2)
#define KVB (128 * ASB)
#define ATT_SMEM ((128 + 256) * ASB + 256)
#define SCL2E 0.18033688011112042f     // 0.125 * log2(e)

__global__ void __launch_bounds__(256, 2) attn_tc(const __half* __restrict__ qkv,
                                                  const int* __restrict__ tdp,
                                                  __half* __restrict__ out) {
    extern __shared__ char smemraw[];
    __half* Qs  = (__half*)smemraw;
    __half* KV0 = Qs + 128 * AS2;
    __half* kmaskS = KV0 + 2 * 128 * AS2;

    const int qb = gridDim.x - 1 - blockIdx.x;   // longest tiles first
    const int bh = blockIdx.y;
    const int b = bh >> 4, h = bh & 15;
    const int TD = tdp[0];
    const int tid = threadIdx.x, w = tid >> 5, lane = tid & 31;
    const int g = lane >> 2, t = lane & 3;

    const size_t base = (size_t)b * SS * E3 + (size_t)h * DH;
    const uint32_t kvBase = smem_u32(KV0);

    const uint32_t qLd = smem_u32(Qs) +
        (w * 16 + (lane & 15)) * ASB + ((lane >> 4) << 4);
    const uint32_t kLd0 = kvBase +
        ((lane & 7) + ((lane >> 4) << 3)) * ASB + (((lane >> 3) & 1) << 4);
    const uint32_t vLd0 = kvBase + 64 * ASB +
        (lane & 15) * ASB + ((lane >> 4) << 4);

    for (int i = tid; i < 128 * 8; i += 256) {
        int r = i >> 3, c = (i & 7) * 8;
        *(uint4*)(Qs + r * AS2 + c) =
            *(const uint4*)(qkv + base + (size_t)(qb * 128 + r) * E3 + c);
    }

    auto load_kv = [&](int kb, int buf) {
        const uint32_t dst = kvBase + buf * KVB;
        #pragma unroll
        for (int i = 0; i < 2; i++) {
            int chunk = tid + i * 256;
            int r = chunk >> 3, cB = (chunk & 7) << 4;
            size_t off = base + (size_t)(kb * 64 + r) * E3 + (cB >> 1);
            cp16(dst + r * ASB + cB,            qkv + off + EE);
            cp16(dst + 64 * ASB + r * ASB + cB, qkv + off + 2 * EE);
        }
        if (tid < 64) {
            int col = kb * 64 + tid;
            kmaskS[buf * 64 + tid] =
                ((col % TD) == TD - 1) ? __float2half(0.0f) : __float2half(1.0f);
        }
    };

    float m0 = -1e30f, m1 = -1e30f, l0 = 0.0f, l1 = 0.0f;
    float o[8][4];
    #pragma unroll
    for (int ni = 0; ni < 8; ni++)
        #pragma unroll
        for (int j = 0; j < 4; j++) o[ni][j] = 0.0f;

    const int ig0 = qb * 128 + w * 16 + g;
    const int ig1 = ig0 + 8;
    const int nkt = 2 * qb + 2;

    load_kv(0, 0); CP_COMMIT;

    for (int kb = 0; kb < nkt; kb++) {
        const int buf = kb & 1;
        CP_WAIT0;
        __syncthreads();
        if (kb + 1 < nkt) load_kv(kb + 1, buf ^ 1);
        CP_COMMIT;

        const uint32_t kLd = kLd0 + buf * KVB;
        const uint32_t vLd = vLd0 + buf * KVB;

        float s[8][4];
        #pragma unroll
        for (int ni = 0; ni < 8; ni++)
            #pragma unroll
            for (int j = 0; j < 4; j++) s[ni][j] = 0.0f;

        #pragma unroll
        for (int ks = 0; ks < 4; ks++) {
            const uint32_t ko = ks * 32;
            uint32_t aq[4];
            LDSM4(aq, qLd + ko);
            #pragma unroll
            for (int p = 0; p < 4; p++) {
                uint32_t bk[4];
                LDSM4(bk, kLd + p * 16 * ASB + ko);
                mmah(s[2 * p],     aq, bk[0], bk[1]);
                mmah(s[2 * p + 1], aq, bk[2], bk[3]);
            }
        }

        // scale into log2 units (+ causal mask on the diagonal chunks)
        if (kb >= nkt - 2) {
            const int colb = kb * 64 + t * 2;
            #pragma unroll
            for (int ni = 0; ni < 8; ni++) {
                #pragma unroll
                for (int j = 0; j < 2; j++) {
                    const int col = colb + ni * 8 + j;
                    s[ni][j]     = (col > ig0) ? -1e30f : s[ni][j] * SCL2E;
                    s[ni][2 + j] = (col > ig1) ? -1e30f : s[ni][2 + j] * SCL2E;
                }
            }
        } else {
            #pragma unroll
            for (int ni = 0; ni < 8; ni++)
                #pragma unroll
                for (int j = 0; j < 4; j++) s[ni][j] *= SCL2E;
        }

        float rm0 = -1e30f, rm1 = -1e30f;
        #pragma unroll
        for (int ni = 0; ni < 8; ni++) {
            rm0 = fmaxf(rm0, fmaxf(s[ni][0], s[ni][1]));
            rm1 = fmaxf(rm1, fmaxf(s[ni][2], s[ni][3]));
        }
        #pragma unroll
        for (int ofs = 1; ofs < 4; ofs <<= 1) {
            rm0 = fmaxf(rm0, __shfl_xor_sync(0xffffffffu, rm0, ofs));
            rm1 = fmaxf(rm1, __shfl_xor_sync(0xffffffffu, rm1, ofs));
        }
        const float nm0 = fmaxf(m0, rm0), nm1 = fmaxf(m1, rm1);
        const float a0 = exp2f(m0 - nm0), a1 = exp2f(m1 - nm1);

        // P = exp2(s - m) computed at fp16 via h2exp2; mask in half2.
        const __half2* km = (const __half2*)(kmaskS + buf * 64) + t;
        uint32_t ph[8][2];
        float rs0 = 0.0f, rs1 = 0.0f;
        #pragma unroll
        for (int ni = 0; ni < 8; ni++) {
            const __half2 mk2 = km[ni * 4];
            __half2 e0 = h2exp2(__floats2half2_rn(s[ni][0] - nm0, s[ni][1] - nm0));
            __half2 e1 = h2exp2(__floats2half2_rn(s[ni][2] - nm1, s[ni][3] - nm1));
            e0 = __hmul2(e0, mk2);
            e1 = __hmul2(e1, mk2);
            ph[ni][0] = *(uint32_t*)&e0;
            ph[ni][1] = *(uint32_t*)&e1;
            float2 f0 = __half22float2(e0);
            float2 f1 = __half22float2(e1);
            rs0 += f0.x + f0.y;
            rs1 += f1.x + f1.y;
        }
        #pragma unroll
        for (int ofs = 1; ofs < 4; ofs <<= 1) {
            rs0 += __shfl_xor_sync(0xffffffffu, rs0, ofs);
            rs1 += __shfl_xor_sync(0xffffffffu, rs1, ofs);
        }
        l0 = l0 * a0 + rs0;
        l1 = l1 * a1 + rs1;
        if (nm0 > m0 || nm1 > m1) {
            #pragma unroll
            for (int ni = 0; ni < 8; ni++) {
                o[ni][0] *= a0; o[ni][1] *= a0;
                o[ni][2] *= a1; o[ni][3] *= a1;
            }
        }
        m0 = nm0; m1 = nm1;

        // O += P @ V (A-fragments are the h2exp2 outputs; V via ldmatrix.trans)
        #pragma unroll
        for (int ks = 0; ks < 4; ks++) {
            uint32_t a[4];
            a[0] = ph[2 * ks][0];
            a[1] = ph[2 * ks][1];
            a[2] = ph[2 * ks + 1][0];
            a[3] = ph[2 * ks + 1][1];
            const uint32_t vBase = vLd + ks * 16 * ASB;
            #pragma unroll
            for (int db = 0; db < 4; db++) {
                uint32_t bv[4];
                LDSM4T(bv, vBase + db * 32);
                mmah(o[2 * db],     a, bv[0], bv[1]);
                mmah(o[2 * db + 1], a, bv[2], bv[3]);
            }
        }
    }

    const float inv0 = 1.0f / l0, inv1 = 1.0f / l1;
    const size_t r0o = ((size_t)(b * SS + qb * 128 + w * 16 + g)) * EE + h * DH;
    const size_t r1o = r0o + 8 * EE;
    #pragma unroll
    for (int ni = 0; ni < 8; ni++) {
        const int c = ni * 8 + t * 2;
        *(__half2*)(out + r0o + c) = __floats2half2_rn(o[ni][0] * inv0, o[ni][1] * inv0);
        *(__half2*)(out + r1o + c) = __floats2half2_rn(o[ni][2] * inv1, o[ni][3] * inv1);
    }
}

// ---------------------------------------------------------------------------
// Launch
// ---------------------------------------------------------------------------
extern "C" void kernel_launch(void* const* d_in, const int* in_sizes, int n_in,
                              void* d_out, int out_size) {
    const float* x      = (const float*)d_in[0];
    const int*   td     = (const int*)d_in[1];
    const float* ln1_g  = (const float*)d_in[2];
    const float* ln1_b  = (const float*)d_in[3];
    const float* ln2_g  = (const float*)d_in[4];
    const float* ln2_b  = (const float*)d_in[5];
    const float* w_qkv  = (const float*)d_in[6];
    const float* b_qkv  = (const float*)d_in[7];
    const float* w_o    = (const float*)d_in[8];
    const float* b_o    = (const float*)d_in[9];
    const float* w_fc1  = (const float*)d_in[10];
    const float* b_fc1  = (const float*)d_in[11];
    const float* w_fc2  = (const float*)d_in[12];
    const float* b_fc2  = (const float*)d_in[13];
    float* out = (float*)d_out;

    __half *xn, *qkvb, *attnb, *fc1b, *wc;
    float *x2;
    cudaGetSymbolAddress((void**)&xn,    g_xn);
    cudaGetSymbolAddress((void**)&qkvb,  g_qkv);
    cudaGetSymbolAddress((void**)&attnb, g_attn);
    cudaGetSymbolAddress((void**)&x2,    g_x2);
    cudaGetSymbolAddress((void**)&fc1b,  g_fc1);
    cudaGetSymbolAddress((void**)&wc,    g_wc);

    __half* wc_qkv = wc;
    __half* wc_o   = wc + (size_t)3 * M1;
    __half* wc_fc1 = wc + (size_t)4 * M1;
    __half* wc_fc2 = wc + (size_t)8 * M1;

    cudaFuncSetAttribute(gemm_mma<0>, cudaFuncAttributeMaxDynamicSharedMemorySize, GEMM_SMEM);
    cudaFuncSetAttribute(gemm_mma<1>, cudaFuncAttributeMaxDynamicSharedMemorySize, GEMM_SMEM);
    cudaFuncSetAttribute(gemm_mma<2>, cudaFuncAttributeMaxDynamicSharedMemorySize, GEMM_SMEM);
    cudaFuncSetAttribute(attn_tc, cudaFuncAttributeMaxDynamicSharedMemorySize, ATT_SMEM);

    // 0. Convert all weights to fp16, one launch
    cvt_all_kernel<<<12 * M1 / 8 / 256, 256>>>(w_qkv, w_o, w_fc1, w_fc2, wc);

    // 1. LN1 -> fp16
    ln_kernel<<<MM, 256>>>(x, ln1_g, ln1_b, xn);
    // 2. QKV projection -> fp16
    gemm_mma<0><<<dim3(E3 / BN, MM / BM), 256, GEMM_SMEM>>>(xn, wc_qkv, b_qkv, nullptr,
                                                            qkvb, MM, E3, EE);
    // 3. FP16 tensor-core attention -> fp16
    attn_tc<<<dim3(SS / 128, BB * HH), 256, ATT_SMEM>>>(qkvb, td, attnb);
    // 4. O projection + residual -> fp32
    gemm_mma<1><<<dim3(EE / BN, MM / BM), 256, GEMM_SMEM>>>(attnb, wc_o, b_o, x,
                                                            x2, MM, EE, EE);
    // 5. LN2 -> fp16
    ln_kernel<<<MM, 256>>>(x2, ln2_g, ln2_b, xn);
    // 6. FC1 + GELU -> fp16
    gemm_mma<2><<<dim3(FFD / BN, MM / BM), 256, GEMM_SMEM>>>(xn, wc_fc1, b_fc1, nullptr,
                                                             fc1b, MM, FFD, EE);
    // 7. FC2 + residual -> fp32 out
    gemm_mma<1><<<dim3(EE / BN, MM / BM), 256, GEMM_SMEM>>>(fc1b, wc_fc2, b_fc2, x2,
                                                            out, MM, EE, FFD);
}